// round 1
// baseline (speedup 1.0000x reference)
#include <cuda_runtime.h>
#include <cuda_bf16.h>

#define LOG2E 1.4426950408889634f

__global__ void initlayer_kernel(const float* __restrict__ R,
                                 const float* __restrict__ coords,
                                 const float* __restrict__ W,
                                 float* __restrict__ out,
                                 int A, int G) {
    extern __shared__ float4 sp[];  // A entries: transformed atoms for batch b

    const int b = blockIdx.y;
    const int g = blockIdx.x * blockDim.x + threadIdx.x;

    // Load 3x3 weight (row-major [m][l]); broadcast via L1.
    const float w00 = W[0], w01 = W[1], w02 = W[2];
    const float w10 = W[3], w11 = W[4], w12 = W[5];
    const float w20 = W[6], w21 = W[7], w22 = W[8];

    // Each block transforms this batch's atoms into shared memory:
    // p[a] = W @ R[b,a]
    for (int a = threadIdx.x; a < A; a += blockDim.x) {
        const float* r = R + ((long)b * A + a) * 3;
        float rx = r[0], ry = r[1], rz = r[2];
        float px = fmaf(w00, rx, fmaf(w01, ry, w02 * rz));
        float py = fmaf(w10, rx, fmaf(w11, ry, w12 * rz));
        float pz = fmaf(w20, rx, fmaf(w21, ry, w22 * rz));
        sp[a] = make_float4(px, py, pz, 0.0f);
    }
    __syncthreads();

    if (g >= G) return;

    // q = W @ coords[g]
    const float cx = coords[g * 3 + 0];
    const float cy = coords[g * 3 + 1];
    const float cz = coords[g * 3 + 2];
    const float qx = fmaf(w00, cx, fmaf(w01, cy, w02 * cz));
    const float qy = fmaf(w10, cx, fmaf(w11, cy, w12 * cz));
    const float qz = fmaf(w20, cx, fmaf(w21, cy, w22 * cz));

    float acc0 = 0.0f, acc1 = 0.0f, acc2 = 0.0f, acc3 = 0.0f;

    int a = 0;
    for (; a + 4 <= A; a += 4) {
        float accs[4];
        #pragma unroll
        for (int j = 0; j < 4; ++j) {
            float4 p = sp[a + j];
            float dx = qx - p.x;
            float dy = qy - p.y;
            float dz = qz - p.z;
            float s = fmaf(dx, dx, fmaf(dy, dy, dz * dz));
            float d;
            asm("sqrt.approx.f32 %0, %1;" : "=f"(d) : "f"(s));
            float e;
            asm("ex2.approx.f32 %0, %1;" : "=f"(e) : "f"(d * LOG2E));
            accs[j] = e;
        }
        acc0 += accs[0];
        acc1 += accs[1];
        acc2 += accs[2];
        acc3 += accs[3];
    }
    // Tail (A not multiple of 4)
    for (; a < A; ++a) {
        float4 p = sp[a];
        float dx = qx - p.x;
        float dy = qy - p.y;
        float dz = qz - p.z;
        float s = fmaf(dx, dx, fmaf(dy, dy, dz * dz));
        float d;
        asm("sqrt.approx.f32 %0, %1;" : "=f"(d) : "f"(s));
        float e;
        asm("ex2.approx.f32 %0, %1;" : "=f"(e) : "f"(d * LOG2E));
        acc0 += e;
    }

    out[(long)b * G + g] = (acc0 + acc1) + (acc2 + acc3);
}

extern "C" void kernel_launch(void* const* d_in, const int* in_sizes, int n_in,
                              void* d_out, int out_size) {
    const float* R      = (const float*)d_in[0];  // (B, A, 3) f32
    const float* coords = (const float*)d_in[1];  // (G, 3)    f32
    const float* W      = (const float*)d_in[2];  // (3, 3)    f32
    // d_in[3] = Z (int32, A entries) — unused by the math, defines A.

    const int A = in_sizes[3];
    const int B = in_sizes[0] / (3 * A);
    const int G = in_sizes[1] / 3;

    float* out = (float*)d_out;  // (B, G) f32

    const int threads = 256;
    dim3 grid((G + threads - 1) / threads, B);
    size_t smem = (size_t)A * sizeof(float4);

    initlayer_kernel<<<grid, threads, smem>>>(R, coords, W, out, A, G);
}

// round 2
// speedup vs baseline: 1.0770x; 1.0770x over previous
#include <cuda_runtime.h>
#include <cuda_bf16.h>

#define LOG2E 1.4426950408889634f

__global__ __launch_bounds__(128)
void initlayer_kernel(const float* __restrict__ R,
                      const float* __restrict__ coords,
                      const float* __restrict__ W,
                      float* __restrict__ out,
                      int A, int G) {
    extern __shared__ float4 sp[];  // A entries: (p'x, p'y, p'z, |p'|^2), p' = log2e*W@R[b,a]

    const int b = blockIdx.y;
    const int g = blockIdx.x * blockDim.x + threadIdx.x;

    // 3x3 weight pre-scaled by log2(e): ||W'(c-r)|| = log2e * ||W(c-r)||,
    // so exp(d) == ex2(||q' - p'||).
    const float w00 = W[0] * LOG2E, w01 = W[1] * LOG2E, w02 = W[2] * LOG2E;
    const float w10 = W[3] * LOG2E, w11 = W[4] * LOG2E, w12 = W[5] * LOG2E;
    const float w20 = W[6] * LOG2E, w21 = W[7] * LOG2E, w22 = W[8] * LOG2E;

    // Block prologue: transform this batch's atoms, store (p', |p'|^2).
    for (int a = threadIdx.x; a < A; a += blockDim.x) {
        const float* r = R + ((long)b * A + a) * 3;
        float rx = r[0], ry = r[1], rz = r[2];
        float px = fmaf(w00, rx, fmaf(w01, ry, w02 * rz));
        float py = fmaf(w10, rx, fmaf(w11, ry, w12 * rz));
        float pz = fmaf(w20, rx, fmaf(w21, ry, w22 * rz));
        float pn = fmaf(px, px, fmaf(py, py, pz * pz));
        sp[a] = make_float4(px, py, pz, pn);
    }
    __syncthreads();

    if (g >= G) return;

    // q' = log2e * W @ coords[g]; keep -2*q' and |q'|^2.
    const float cx = coords[g * 3 + 0];
    const float cy = coords[g * 3 + 1];
    const float cz = coords[g * 3 + 2];
    const float qx = fmaf(w00, cx, fmaf(w01, cy, w02 * cz));
    const float qy = fmaf(w10, cx, fmaf(w11, cy, w12 * cz));
    const float qz = fmaf(w20, cx, fmaf(w21, cy, w22 * cz));
    const float qn  = fmaf(qx, qx, fmaf(qy, qy, qz * qz));
    const float m2x = -2.0f * qx;
    const float m2y = -2.0f * qy;
    const float m2z = -2.0f * qz;

    float acc0 = 0.0f, acc1 = 0.0f, acc2 = 0.0f, acc3 = 0.0f;

    int a = 0;
    for (; a + 4 <= A; a += 4) {
        float accs[4];
        #pragma unroll
        for (int j = 0; j < 4; ++j) {
            float4 p = sp[a + j];
            // s = |q'|^2 + |p'|^2 - 2 q'.p'   (expanded squared distance)
            float s = fmaf(m2x, p.x, fmaf(m2y, p.y, fmaf(m2z, p.z, qn + p.w)));
            s = fmaxf(s, 0.0f);  // guard cancellation -> sqrt of negative
            float d;
            asm("sqrt.approx.f32 %0, %1;" : "=f"(d) : "f"(s));
            float e;
            asm("ex2.approx.f32 %0, %1;" : "=f"(e) : "f"(d));
            accs[j] = e;
        }
        acc0 += accs[0];
        acc1 += accs[1];
        acc2 += accs[2];
        acc3 += accs[3];
    }
    for (; a < A; ++a) {
        float4 p = sp[a];
        float s = fmaf(m2x, p.x, fmaf(m2y, p.y, fmaf(m2z, p.z, qn + p.w)));
        s = fmaxf(s, 0.0f);
        float d;
        asm("sqrt.approx.f32 %0, %1;" : "=f"(d) : "f"(s));
        float e;
        asm("ex2.approx.f32 %0, %1;" : "=f"(e) : "f"(d));
        acc0 += e;
    }

    out[(long)b * G + g] = (acc0 + acc1) + (acc2 + acc3);
}

extern "C" void kernel_launch(void* const* d_in, const int* in_sizes, int n_in,
                              void* d_out, int out_size) {
    const float* R      = (const float*)d_in[0];  // (B, A, 3) f32
    const float* coords = (const float*)d_in[1];  // (G, 3)    f32
    const float* W      = (const float*)d_in[2];  // (3, 3)    f32

    const int A = in_sizes[3];
    const int B = in_sizes[0] / (3 * A);
    const int G = in_sizes[1] / 3;

    float* out = (float*)d_out;  // (B, G) f32

    const int threads = 128;  // small CTAs: 1024 blocks -> 1.2% wave imbalance
    dim3 grid((G + threads - 1) / threads, B);
    size_t smem = (size_t)A * sizeof(float4);

    initlayer_kernel<<<grid, threads, smem>>>(R, coords, W, out, A, G);
}